// round 16
// baseline (speedup 1.0000x reference)
#include <cuda_runtime.h>
#include <math.h>
#include <stdint.h>

// Problem constants
#define BB   2
#define T1C  2048
#define T2C  2048
#define DD   1024
#define HH   16
#define HDC  64
#define MPROJ (BB * T1C)       // 4096

// Scratch (device globals: no allocation allowed)
__device__ float g_q[BB * T1C * DD];
__device__ float g_k[BB * T2C * DD];
__device__ float g_v[BB * T2C * DD];
__device__ float g_ctx[BB * T1C * DD];
__device__ float g_maskbias[BB * T2C];
__device__ float g_rowsum[BB * HH * T1C];
// Pre-rounded (tf32-valued fp32) copies of external mma inputs
__device__ float g_rq[BB * T1C * DD];
__device__ float g_rk[BB * T2C * DD];
__device__ float g_rv[BB * T2C * DD];
__device__ float g_rwq[DD * DD];
__device__ float g_rwk[DD * DD];
__device__ float g_rwv[DD * DD];
__device__ float g_rwo[DD * DD];

// ---------------------------------------------------------------------------
// Helpers. Every value entering an mma is pre-rounded to a tf32-representable
// f32; mainloops feed raw bits (truncation of an already-tf32 value ==
// identity). Proven: rel_err 2.684e-4.
// ---------------------------------------------------------------------------
__device__ __forceinline__ float rndf(float f) {
    unsigned u;
    asm("cvt.rna.tf32.f32 %0, %1;" : "=r"(u) : "f"(f));
    return __uint_as_float(u);
}

__device__ __forceinline__ void mma_tf32(float* d, const unsigned* a, const unsigned* b) {
    asm volatile(
        "mma.sync.aligned.m16n8k8.row.col.f32.tf32.tf32.f32 "
        "{%0,%1,%2,%3}, {%4,%5,%6,%7}, {%8,%9}, {%0,%1,%2,%3};\n"
        : "+f"(d[0]), "+f"(d[1]), "+f"(d[2]), "+f"(d[3])
        : "r"(a[0]), "r"(a[1]), "r"(a[2]), "r"(a[3]), "r"(b[0]), "r"(b[1]));
}

__device__ __forceinline__ void cp16(void* dst, const void* src) {
    unsigned d = (unsigned)__cvta_generic_to_shared(dst);
    asm volatile("cp.async.cg.shared.global [%0], [%1], 16;\n" :: "r"(d), "l"(src));
}
#define CP_COMMIT asm volatile("cp.async.commit_group;\n" ::: "memory")
#define CP_WAIT0  asm volatile("cp.async.wait_group 0;\n" ::: "memory")

// ---------------------------------------------------------------------------
// Pre-round branch A + fused prep: z=0..3 round (q, k, wq, wk); z=4 does the
// mask conversion (dtype auto-detect) + rowsum zeroing. One launch replaces
// the former prep_mask + roundA pair on the critical path.
// ---------------------------------------------------------------------------
__global__ void roundA_kernel(const float* __restrict__ q,
                              const float* __restrict__ k,
                              const float* __restrict__ wq,
                              const float* __restrict__ wk,
                              const unsigned char* __restrict__ mraw) {
    if (blockIdx.z == 4) {
        if (blockIdx.x == 0) {
            __shared__ int cnt;
            if (threadIdx.x == 0) cnt = 0;
            __syncthreads();
            int local = 0;
            for (int i = threadIdx.x; i < 1024; i += blockDim.x)
                if (mraw[4 * i + 1] != 0) local++;
            if (local) atomicAdd(&cnt, local);
            __syncthreads();
            const bool isU8 = (cnt > 0);
            const unsigned int* mw = (const unsigned int*)mraw;
            for (int i = threadIdx.x; i < BB * T2C; i += blockDim.x) {
                bool m = isU8 ? (mraw[i] != 0) : (mw[i] != 0u);
                g_maskbias[i] = m ? -1e9f : 0.0f;
            }
        }
        int i = blockIdx.x * blockDim.x + threadIdx.x;
        if (i < BB * HH * T1C) g_rowsum[i] = 0.0f;
        return;
    }

    const float* src;
    float* dst;
    int n;
    switch (blockIdx.z) {
        case 0: src = q;  dst = g_rq;  n = BB * T1C * DD; break;
        case 1: src = k;  dst = g_rk;  n = BB * T2C * DD; break;
        case 2: src = wq; dst = g_rwq; n = DD * DD; break;
        default: src = wk; dst = g_rwk; n = DD * DD; break;
    }
    int i4 = blockIdx.x * blockDim.x + threadIdx.x;
    if (i4 * 4 >= n) return;
    float4 x = *(const float4*)&src[i4 * 4];
    x.x = rndf(x.x); x.y = rndf(x.y); x.z = rndf(x.z); x.w = rndf(x.w);
    *(float4*)&dst[i4 * 4] = x;
}

__global__ void roundB_kernel(const float* __restrict__ v,
                              const float* __restrict__ wv,
                              const float* __restrict__ wo) {
    const float* src;
    float* dst;
    int n;
    switch (blockIdx.z) {
        case 0: src = v;  dst = g_rv;  n = BB * T2C * DD; break;
        case 1: src = wv; dst = g_rwv; n = DD * DD; break;
        default: src = wo; dst = g_rwo; n = DD * DD; break;
    }
    int i4 = blockIdx.x * blockDim.x + threadIdx.x;
    if (i4 * 4 >= n) return;
    float4 x = *(const float4*)&src[i4 * 4];
    x.x = rndf(x.x); x.y = rndf(x.y); x.z = rndf(x.z); x.w = rndf(x.w);
    *(float4*)&dst[i4 * 4] = x;
}

// ---------------------------------------------------------------------------
// tf32 GEMM + bias, cp.async double-buffered, BK=32, up to 3 problems via
// blockIdx.z. Dynamic smem: As[2][128][36] + Bs[2][32][136] = 71680 bytes.
// ---------------------------------------------------------------------------
__global__ __launch_bounds__(256, 2) void gemm3_tf32_kernel(
    const float* __restrict__ A0, const float* __restrict__ W0,
    const float* __restrict__ b0, float* __restrict__ C0,
    const float* __restrict__ A1, const float* __restrict__ W1,
    const float* __restrict__ b1, float* __restrict__ C1,
    const float* __restrict__ A2, const float* __restrict__ W2,
    const float* __restrict__ b2, float* __restrict__ C2,
    int rnd) {
    extern __shared__ unsigned smg[];
    unsigned (*As)[128][36] = (unsigned(*)[128][36])smg;
    unsigned (*Bs)[32][136] = (unsigned(*)[32][136])(smg + 2 * 128 * 36);

    const float *A, *W, *bias;
    float* C;
    if (blockIdx.z == 0)      { A = A0; W = W0; bias = b0; C = C0; }
    else if (blockIdx.z == 1) { A = A1; W = W1; bias = b1; C = C1; }
    else                      { A = A2; W = W2; bias = b2; C = C2; }

    const int tid  = threadIdx.x;
    const int warp = tid >> 5, lane = tid & 31;
    const int g = lane >> 2, tg = lane & 3;
    const int wm = (warp & 1) * 64, wn = (warp >> 1) * 32;
    const int bm = blockIdx.y * 128, bn = blockIdx.x * 128;

    auto load_stage = [&](int nb, int k0) {
#pragma unroll
        for (int it = 0; it < 4; it++) {
            int idx = it * 256 + tid;
            int ar = idx >> 3, au = idx & 7;
            cp16(&As[nb][ar][au * 4], &A[(size_t)(bm + ar) * 1024 + k0 + au * 4]);
            int br = idx >> 5, bu = idx & 31;
            cp16(&Bs[nb][br][bu * 4], &W[(size_t)(k0 + br) * 1024 + bn + bu * 4]);
        }
        CP_COMMIT;
    };

    load_stage(0, 0);

    float acc[4][4][4] = {};

    for (int k0 = 0; k0 < 1024; k0 += 32) {
        const int buf = (k0 >> 5) & 1;
        CP_WAIT0;
        __syncthreads();
        if (k0 + 32 < 1024) load_stage(buf ^ 1, k0 + 32);
#pragma unroll
        for (int ks = 0; ks < 4; ks++) {
            const int kb = ks * 8;
            unsigned af[4][4], bf[4][2];
#pragma unroll
            for (int mt = 0; mt < 4; mt++) {
                int r = wm + mt * 16;
                af[mt][0] = As[buf][r + g][kb + tg];
                af[mt][1] = As[buf][r + g + 8][kb + tg];
                af[mt][2] = As[buf][r + g][kb + tg + 4];
                af[mt][3] = As[buf][r + g + 8][kb + tg + 4];
            }
#pragma unroll
            for (int nt = 0; nt < 4; nt++) {
                int c = wn + nt * 8 + g;
                bf[nt][0] = Bs[buf][kb + tg][c];
                bf[nt][1] = Bs[buf][kb + tg + 4][c];
            }
#pragma unroll
            for (int mt = 0; mt < 4; mt++)
#pragma unroll
                for (int nt = 0; nt < 4; nt++)
                    mma_tf32(acc[mt][nt], af[mt], bf[nt]);
        }
    }

#pragma unroll
    for (int mt = 0; mt < 4; mt++) {
        int r0 = bm + wm + mt * 16 + g;
#pragma unroll
        for (int nt = 0; nt < 4; nt++) {
            int c0 = bn + wn + nt * 8 + tg * 2;
            float bb0 = bias[c0], bb1 = bias[c0 + 1];
            float v00 = acc[mt][nt][0] + bb0, v01 = acc[mt][nt][1] + bb1;
            float v10 = acc[mt][nt][2] + bb0, v11 = acc[mt][nt][3] + bb1;
            if (rnd) {
                v00 = rndf(v00); v01 = rndf(v01);
                v10 = rndf(v10); v11 = rndf(v11);
            }
            C[(size_t)r0 * 1024 + c0]           = v00;
            C[(size_t)r0 * 1024 + c0 + 1]       = v01;
            C[(size_t)(r0 + 8) * 1024 + c0]     = v10;
            C[(size_t)(r0 + 8) * 1024 + c0 + 1] = v11;
        }
    }
}

// ---------------------------------------------------------------------------
// Scores + exp. 64(q) x 128(k) per CTA, 3/SM. bh0 selects the batch half.
// Dynamic smem: Qs[64][68] + Ks[128][68] = 52224 bytes.
// ---------------------------------------------------------------------------
__global__ __launch_bounds__(256, 3) void scores_exp_tf32_kernel(
    const float* __restrict__ q, const float* __restrict__ k,
    float* __restrict__ attn, int bh0) {
    extern __shared__ unsigned sm[];
    unsigned (*Qs)[68] = (unsigned(*)[68])sm;             // [64][68]
    unsigned (*Ks)[68] = (unsigned(*)[68])(sm + 64 * 68); // [128][68]
    __shared__ float rowred[64];

    const int tid  = threadIdx.x;
    const int warp = tid >> 5, lane = tid & 31;
    const int g = lane >> 2, tg = lane & 3;
    const int wm = (warp & 1) * 32, wn = (warp >> 1) * 32;
    const int bh = blockIdx.z + bh0;
    const int b = bh >> 4, h = bh & 15;
    const int qi0 = blockIdx.y * 64, ki0 = blockIdx.x * 128;
    const float* qb = q + (size_t)b * T1C * DD + h * HDC;
    const float* kb = k + (size_t)b * T2C * DD + h * HDC;

    if (tid < 64) rowred[tid] = 0.0f;

#pragma unroll
    for (int i = 0; i < 4; i++) {
        int idx = tid + i * 256;
        int row = idx >> 4, c4 = (idx & 15) * 4;
        cp16(&Qs[row][c4], &qb[(size_t)(qi0 + row) * DD + c4]);
    }
#pragma unroll
    for (int i = 0; i < 8; i++) {
        int idx = tid + i * 256;
        int row = idx >> 4, c4 = (idx & 15) * 4;
        cp16(&Ks[row][c4], &kb[(size_t)(ki0 + row) * DD + c4]);
    }
    CP_COMMIT;
    CP_WAIT0;
    __syncthreads();

    float acc[2][4][4] = {};
#pragma unroll
    for (int kc = 0; kc < 8; kc++) {
        const int kbk = kc * 8;
        unsigned af[2][4], bf[4][2];
#pragma unroll
        for (int mt = 0; mt < 2; mt++) {
            int r = wm + mt * 16;
            af[mt][0] = Qs[r + g][kbk + tg];
            af[mt][1] = Qs[r + g + 8][kbk + tg];
            af[mt][2] = Qs[r + g][kbk + tg + 4];
            af[mt][3] = Qs[r + g + 8][kbk + tg + 4];
        }
#pragma unroll
        for (int nt = 0; nt < 4; nt++) {
            int c = wn + nt * 8 + g;
            bf[nt][0] = Ks[c][kbk + tg];
            bf[nt][1] = Ks[c][kbk + tg + 4];
        }
#pragma unroll
        for (int mt = 0; mt < 2; mt++)
#pragma unroll
            for (int nt = 0; nt < 4; nt++)
                mma_tf32(acc[mt][nt], af[mt], bf[nt]);
    }

    float* outp = attn + ((size_t)bh * T1C + qi0) * T2C + ki0;
    const float* mb = &g_maskbias[b * T2C + ki0];
#pragma unroll
    for (int mt = 0; mt < 2; mt++) {
        int r0 = wm + mt * 16 + g;
        float rp0 = 0.0f, rp1 = 0.0f;
#pragma unroll
        for (int nt = 0; nt < 4; nt++) {
            int c0 = wn + nt * 8 + tg * 2;
            float m0 = mb[c0], m1 = mb[c0 + 1];
            float2 e0, e1;
            e0.x = rndf(__expf(acc[mt][nt][0] * 0.125f + m0));
            e0.y = rndf(__expf(acc[mt][nt][1] * 0.125f + m1));
            e1.x = rndf(__expf(acc[mt][nt][2] * 0.125f + m0));
            e1.y = rndf(__expf(acc[mt][nt][3] * 0.125f + m1));
            *(float2*)&outp[(size_t)r0 * T2C + c0]       = e0;
            *(float2*)&outp[(size_t)(r0 + 8) * T2C + c0] = e1;
            rp0 += e0.x + e0.y;
            rp1 += e1.x + e1.y;
        }
        rp0 += __shfl_xor_sync(0xffffffffu, rp0, 1);
        rp0 += __shfl_xor_sync(0xffffffffu, rp0, 2);
        rp1 += __shfl_xor_sync(0xffffffffu, rp1, 1);
        rp1 += __shfl_xor_sync(0xffffffffu, rp1, 2);
        if (tg == 0) {
            atomicAdd(&rowred[r0], rp0);
            atomicAdd(&rowred[r0 + 8], rp1);
        }
    }
    __syncthreads();
    if (tid < 64)
        atomicAdd(&g_rowsum[(size_t)bh * T1C + qi0 + tid], rowred[tid]);
}

// ---------------------------------------------------------------------------
// Fused normalize + context. bh0 selects the batch half.
// Dynamic smem: As[2][128][36] + Vs[2][32][72] = 55296 bytes.
// ---------------------------------------------------------------------------
__global__ __launch_bounds__(256, 3) void ctx_tf32_kernel(
    float* __restrict__ attn, const float* __restrict__ v,
    float* __restrict__ ctx, int bh0) {
    extern __shared__ unsigned sm[];
    unsigned (*As)[128][36] = (unsigned(*)[128][36])sm;
    unsigned (*Vs)[32][72]  = (unsigned(*)[32][72])(sm + 2 * 128 * 36);
    __shared__ float invs[128];

    const int tid  = threadIdx.x;
    const int warp = tid >> 5, lane = tid & 31;
    const int g = lane >> 2, tg = lane & 3;
    const int wm = (warp & 3) * 32, wn = (warp >> 2) * 32;
    const int bh = blockIdx.y + bh0;
    const int b = bh >> 4, h = bh & 15;
    const int qi0 = blockIdx.x * 128;
    float* pb = attn + ((size_t)bh * T1C + qi0) * T2C;
    const float* vb = v + (size_t)b * T2C * DD + h * HDC;

    if (tid < 128) invs[tid] = 1.0f / g_rowsum[(size_t)bh * T1C + qi0 + tid];

    const int arow = tid >> 3, ac4 = (tid & 7) * 4;
    const int vrow = tid >> 4, vc4 = (tid & 15) * 4;

    {
        cp16(&As[0][arow][ac4],      &pb[(size_t)arow * T2C + ac4]);
        cp16(&As[0][arow + 32][ac4], &pb[(size_t)(arow + 32) * T2C + ac4]);
        cp16(&As[0][arow + 64][ac4], &pb[(size_t)(arow + 64) * T2C + ac4]);
        cp16(&As[0][arow + 96][ac4], &pb[(size_t)(arow + 96) * T2C + ac4]);
        cp16(&Vs[0][vrow][vc4],      &vb[(size_t)vrow * DD + vc4]);
        cp16(&Vs[0][vrow + 16][vc4], &vb[(size_t)(vrow + 16) * DD + vc4]);
        CP_COMMIT;
    }

    float acc[2][4][4] = {};

    for (int j0 = 0; j0 < T2C; j0 += 32) {
        const int buf = (j0 >> 5) & 1;
        CP_WAIT0;
        __syncthreads();
        if (j0 + 32 < T2C) {
            const int nb = buf ^ 1, jn = j0 + 32;
            cp16(&As[nb][arow][ac4],      &pb[(size_t)arow * T2C + jn + ac4]);
            cp16(&As[nb][arow + 32][ac4], &pb[(size_t)(arow + 32) * T2C + jn + ac4]);
            cp16(&As[nb][arow + 64][ac4], &pb[(size_t)(arow + 64) * T2C + jn + ac4]);
            cp16(&As[nb][arow + 96][ac4], &pb[(size_t)(arow + 96) * T2C + jn + ac4]);
            cp16(&Vs[nb][vrow][vc4],      &vb[(size_t)(jn + vrow) * DD + vc4]);
            cp16(&Vs[nb][vrow + 16][vc4], &vb[(size_t)(jn + vrow + 16) * DD + vc4]);
            CP_COMMIT;
        }

#pragma unroll
        for (int i = 0; i < 4; i++) {
            int row = arow + i * 32;
            float s = invs[row];
            float4 p = *(float4*)&As[buf][row][ac4];
            p.x *= s; p.y *= s; p.z *= s; p.w *= s;
            *(float4*)&pb[(size_t)row * T2C + j0 + ac4] = p;
        }

#pragma unroll
        for (int ks = 0; ks < 4; ks++) {
            const int kb = ks * 8;
            unsigned af[2][4], bf[4][2];
#pragma unroll
            for (int mt = 0; mt < 2; mt++) {
                int r = wm + mt * 16;
                af[mt][0] = As[buf][r + g][kb + tg];
                af[mt][1] = As[buf][r + g + 8][kb + tg];
                af[mt][2] = As[buf][r + g][kb + tg + 4];
                af[mt][3] = As[buf][r + g + 8][kb + tg + 4];
            }
#pragma unroll
            for (int nt = 0; nt < 4; nt++) {
                int c = wn + nt * 8 + g;
                bf[nt][0] = Vs[buf][kb + tg][c];
                bf[nt][1] = Vs[buf][kb + tg + 4][c];
            }
#pragma unroll
            for (int mt = 0; mt < 2; mt++)
#pragma unroll
                for (int nt = 0; nt < 4; nt++)
                    mma_tf32(acc[mt][nt], af[mt], bf[nt]);
        }
    }

#pragma unroll
    for (int mt = 0; mt < 2; mt++) {
        int rloc = wm + mt * 16 + g;
        int r0 = qi0 + rloc;
        float s0 = invs[rloc], s1 = invs[rloc + 8];
#pragma unroll
        for (int nt = 0; nt < 4; nt++) {
            int c0 = wn + nt * 8 + tg * 2;
            size_t base0 = (size_t)b * T1C * DD + (size_t)r0 * DD + h * HDC + c0;
            size_t base1 = base0 + (size_t)8 * DD;
            ctx[base0]     = rndf(acc[mt][nt][0] * s0);
            ctx[base0 + 1] = rndf(acc[mt][nt][1] * s0);
            ctx[base1]     = rndf(acc[mt][nt][2] * s1);
            ctx[base1 + 1] = rndf(acc[mt][nt][3] * s1);
        }
    }
}

// ---------------------------------------------------------------------------
extern "C" void kernel_launch(void* const* d_in, const int* in_sizes, int n_in,
                              void* d_out, int out_size) {
    const float* query = (const float*)d_in[0];
    const float* key   = (const float*)d_in[1];
    const float* value = (const float*)d_in[2];
    const unsigned char* mask = (const unsigned char*)d_in[3];
    const float* Wq_w = (const float*)d_in[4];
    const float* Wq_b = (const float*)d_in[5];
    const float* Wk_w = (const float*)d_in[6];
    const float* Wk_b = (const float*)d_in[7];
    const float* Wv_w = (const float*)d_in[8];
    const float* Wv_b = (const float*)d_in[9];
    const float* Wo_w = (const float*)d_in[10];
    const float* Wo_b = (const float*)d_in[11];

    float* out  = (float*)d_out;                          // [B,T1,D]
    float* attn = out + (size_t)BB * T1C * DD;            // [B,H,T1,T2]

    float *gq, *gk, *gv, *gctx;
    float *grq, *grk, *grv, *grwq, *grwk, *grwv, *grwo;
    cudaGetSymbolAddress((void**)&gq,   g_q);
    cudaGetSymbolAddress((void**)&gk,   g_k);
    cudaGetSymbolAddress((void**)&gv,   g_v);
    cudaGetSymbolAddress((void**)&gctx, g_ctx);
    cudaGetSymbolAddress((void**)&grq,  g_rq);
    cudaGetSymbolAddress((void**)&grk,  g_rk);
    cudaGetSymbolAddress((void**)&grv,  g_rv);
    cudaGetSymbolAddress((void**)&grwq, g_rwq);
    cudaGetSymbolAddress((void**)&grwk, g_rwk);
    cudaGetSymbolAddress((void**)&grwv, g_rwv);
    cudaGetSymbolAddress((void**)&grwo, g_rwo);

    const int scores_smem = ((64 + 128) * 68) * 4;                // 52224
    const int ctx_smem    = (2 * 128 * 36 + 2 * 32 * 72) * 4;     // 55296
    const int gemm_smem   = (2 * 128 * 36 + 2 * 32 * 136) * 4;    // 71680
    cudaFuncSetAttribute(scores_exp_tf32_kernel,
                         cudaFuncAttributeMaxDynamicSharedMemorySize, scores_smem);
    cudaFuncSetAttribute(ctx_tf32_kernel,
                         cudaFuncAttributeMaxDynamicSharedMemorySize, ctx_smem);
    cudaFuncSetAttribute(gemm3_tf32_kernel,
                         cudaFuncAttributeMaxDynamicSharedMemorySize, gemm_smem);

    // Side stream + events (created once; host-side resources only).
    static cudaStream_t s2 = 0;
    static cudaEvent_t evF = 0, evRA = 0, evV = 0, evQK1 = 0, evS0 = 0, evDone = 0;
    if (!s2) {
        cudaStreamCreateWithFlags(&s2, cudaStreamNonBlocking);
        cudaEventCreateWithFlags(&evF,    cudaEventDisableTiming);
        cudaEventCreateWithFlags(&evRA,   cudaEventDisableTiming);
        cudaEventCreateWithFlags(&evV,    cudaEventDisableTiming);
        cudaEventCreateWithFlags(&evQK1,  cudaEventDisableTiming);
        cudaEventCreateWithFlags(&evS0,   cudaEventDisableTiming);
        cudaEventCreateWithFlags(&evDone, cudaEventDisableTiming);
    }

    const size_t halfRows = (size_t)T1C * DD;   // elements per batch half

    // Fork side stream.
    cudaEventRecord(evF, 0);
    cudaStreamWaitEvent(s2, evF, 0);

    // ---- Side stream: V path, then batch-1 QK projection ----
    roundB_kernel<<<dim3(4096, 1, 3), 256, 0, s2>>>(value, Wv_w, Wo_w);
    gemm3_tf32_kernel<<<dim3(8, 32, 1), 256, gemm_smem, s2>>>(
        grv, grwv, Wv_b, gv, grv, grwv, Wv_b, gv, grv, grwv, Wv_b, gv, 1);
    cudaEventRecord(evV, s2);

    // ---- Main stream: fused prep+roundA, then batch-0 QK projection ----
    roundA_kernel<<<dim3(4096, 1, 5), 256>>>(query, key, Wq_w, Wk_w, mask);
    cudaEventRecord(evRA, 0);
    gemm3_tf32_kernel<<<dim3(8, 16, 2), 256, gemm_smem>>>(
        grq, grwq, Wq_b, gq, grk, grwk, Wk_b, gk, grk, grwk, Wk_b, gk, 1);

    // Side: batch-1 QK projection (needs roundA).
    cudaStreamWaitEvent(s2, evRA, 0);
    gemm3_tf32_kernel<<<dim3(8, 16, 2), 256, gemm_smem, s2>>>(
        grq + halfRows, grwq, Wq_b, gq + halfRows,
        grk + halfRows, grwk, Wk_b, gk + halfRows,
        grk + halfRows, grwk, Wk_b, gk + halfRows, 1);
    cudaEventRecord(evQK1, s2);

    // Main: scores_b0 (only needs batch-0 q,k).
    scores_exp_tf32_kernel<<<dim3(16, 32, 16), 256, scores_smem>>>(gq, gk, attn, 0);
    cudaEventRecord(evS0, 0);

    // Main: scores_b1 (needs batch-1 q,k from side).
    cudaStreamWaitEvent(0, evQK1, 0);
    scores_exp_tf32_kernel<<<dim3(16, 32, 16), 256, scores_smem>>>(gq, gk, attn, 16);

    // Side: ctx_b0 + outproj_b0 (needs scores_b0 + V; evV already in-stream).
    cudaStreamWaitEvent(s2, evS0, 0);
    ctx_tf32_kernel<<<dim3(16, 16), 256, ctx_smem, s2>>>(attn, gv, gctx, 0);
    gemm3_tf32_kernel<<<dim3(8, 16, 1), 256, gemm_smem, s2>>>(
        gctx, grwo, Wo_b, out, gctx, grwo, Wo_b, out, gctx, grwo, Wo_b, out, 0);
    cudaEventRecord(evDone, s2);

    // Main: ctx_b1 (needs V) + outproj_b1, then join.
    cudaStreamWaitEvent(0, evV, 0);
    ctx_tf32_kernel<<<dim3(16, 16), 256, ctx_smem>>>(attn, gv, gctx, 16);
    gemm3_tf32_kernel<<<dim3(8, 16, 1), 256, gemm_smem>>>(
        gctx + halfRows, grwo, Wo_b, out + halfRows,
        gctx + halfRows, grwo, Wo_b, out + halfRows,
        gctx + halfRows, grwo, Wo_b, out + halfRows, 0);
    cudaStreamWaitEvent(0, evDone, 0);
}

// round 17
// speedup vs baseline: 1.0154x; 1.0154x over previous
#include <cuda_runtime.h>
#include <math.h>
#include <stdint.h>

// Problem constants
#define BB   2
#define T1C  2048
#define T2C  2048
#define DD   1024
#define HH   16
#define HDC  64
#define MPROJ (BB * T1C)       // 4096

// Scratch (device globals: no allocation allowed)
__device__ float g_q[BB * T1C * DD];
__device__ float g_k[BB * T2C * DD];
__device__ float g_v[BB * T2C * DD];
__device__ float g_ctx[BB * T1C * DD];
__device__ float g_maskbias[BB * T2C];
__device__ float g_rowsum[BB * HH * T1C];
// Pre-rounded (tf32-valued fp32) copies of external mma inputs
__device__ float g_rq[BB * T1C * DD];
__device__ float g_rk[BB * T2C * DD];
__device__ float g_rv[BB * T2C * DD];
__device__ float g_rwq[DD * DD];
__device__ float g_rwk[DD * DD];
__device__ float g_rwv[DD * DD];
__device__ float g_rwo[DD * DD];

// ---------------------------------------------------------------------------
// Helpers. Every value entering an mma is pre-rounded to a tf32-representable
// f32; mainloops feed raw bits (truncation of an already-tf32 value ==
// identity). Proven: rel_err 2.684e-4.
// ---------------------------------------------------------------------------
__device__ __forceinline__ float rndf(float f) {
    unsigned u;
    asm("cvt.rna.tf32.f32 %0, %1;" : "=r"(u) : "f"(f));
    return __uint_as_float(u);
}

__device__ __forceinline__ void mma_tf32(float* d, const unsigned* a, const unsigned* b) {
    asm volatile(
        "mma.sync.aligned.m16n8k8.row.col.f32.tf32.tf32.f32 "
        "{%0,%1,%2,%3}, {%4,%5,%6,%7}, {%8,%9}, {%0,%1,%2,%3};\n"
        : "+f"(d[0]), "+f"(d[1]), "+f"(d[2]), "+f"(d[3])
        : "r"(a[0]), "r"(a[1]), "r"(a[2]), "r"(a[3]), "r"(b[0]), "r"(b[1]));
}

__device__ __forceinline__ void cp16(void* dst, const void* src) {
    unsigned d = (unsigned)__cvta_generic_to_shared(dst);
    asm volatile("cp.async.cg.shared.global [%0], [%1], 16;\n" :: "r"(d), "l"(src));
}
#define CP_COMMIT asm volatile("cp.async.commit_group;\n" ::: "memory")
#define CP_WAIT0  asm volatile("cp.async.wait_group 0;\n" ::: "memory")

// ---------------------------------------------------------------------------
// Mask conversion (dtype auto-detect) + rowsum zeroing, one launch.
// ---------------------------------------------------------------------------
__global__ void prep_mask_kernel(const unsigned char* __restrict__ mraw) {
    if (blockIdx.x == 0) {
        __shared__ int cnt;
        if (threadIdx.x == 0) cnt = 0;
        __syncthreads();
        int local = 0;
        for (int i = threadIdx.x; i < 1024; i += blockDim.x)
            if (mraw[4 * i + 1] != 0) local++;
        if (local) atomicAdd(&cnt, local);
        __syncthreads();
        const bool isU8 = (cnt > 0);
        const unsigned int* mw = (const unsigned int*)mraw;
        for (int i = threadIdx.x; i < BB * T2C; i += blockDim.x) {
            bool m = isU8 ? (mraw[i] != 0) : (mw[i] != 0u);
            g_maskbias[i] = m ? -1e9f : 0.0f;
        }
    }
    int i = blockIdx.x * blockDim.x + threadIdx.x;
    if (i < BB * HH * T1C) g_rowsum[i] = 0.0f;
}

// ---------------------------------------------------------------------------
// Pre-round: branch A (q, k, wq, wk) main stream; branch B (v, wv, wo) side.
// ---------------------------------------------------------------------------
__global__ void roundA_kernel(const float* __restrict__ q,
                              const float* __restrict__ k,
                              const float* __restrict__ wq,
                              const float* __restrict__ wk) {
    const float* src;
    float* dst;
    int n;
    switch (blockIdx.z) {
        case 0: src = q;  dst = g_rq;  n = BB * T1C * DD; break;
        case 1: src = k;  dst = g_rk;  n = BB * T2C * DD; break;
        case 2: src = wq; dst = g_rwq; n = DD * DD; break;
        default: src = wk; dst = g_rwk; n = DD * DD; break;
    }
    int i4 = blockIdx.x * blockDim.x + threadIdx.x;
    if (i4 * 4 >= n) return;
    float4 x = *(const float4*)&src[i4 * 4];
    x.x = rndf(x.x); x.y = rndf(x.y); x.z = rndf(x.z); x.w = rndf(x.w);
    *(float4*)&dst[i4 * 4] = x;
}

__global__ void roundB_kernel(const float* __restrict__ v,
                              const float* __restrict__ wv,
                              const float* __restrict__ wo) {
    const float* src;
    float* dst;
    int n;
    switch (blockIdx.z) {
        case 0: src = v;  dst = g_rv;  n = BB * T2C * DD; break;
        case 1: src = wv; dst = g_rwv; n = DD * DD; break;
        default: src = wo; dst = g_rwo; n = DD * DD; break;
    }
    int i4 = blockIdx.x * blockDim.x + threadIdx.x;
    if (i4 * 4 >= n) return;
    float4 x = *(const float4*)&src[i4 * 4];
    x.x = rndf(x.x); x.y = rndf(x.y); x.z = rndf(x.z); x.w = rndf(x.w);
    *(float4*)&dst[i4 * 4] = x;
}

// ---------------------------------------------------------------------------
// tf32 GEMM + bias, cp.async double-buffered, BK=32, up to 3 problems via
// blockIdx.z. Dynamic smem: As[2][128][36] + Bs[2][32][136] = 71680 bytes.
// ---------------------------------------------------------------------------
__global__ __launch_bounds__(256, 2) void gemm3_tf32_kernel(
    const float* __restrict__ A0, const float* __restrict__ W0,
    const float* __restrict__ b0, float* __restrict__ C0,
    const float* __restrict__ A1, const float* __restrict__ W1,
    const float* __restrict__ b1, float* __restrict__ C1,
    const float* __restrict__ A2, const float* __restrict__ W2,
    const float* __restrict__ b2, float* __restrict__ C2,
    int rnd) {
    extern __shared__ unsigned smg[];
    unsigned (*As)[128][36] = (unsigned(*)[128][36])smg;
    unsigned (*Bs)[32][136] = (unsigned(*)[32][136])(smg + 2 * 128 * 36);

    const float *A, *W, *bias;
    float* C;
    if (blockIdx.z == 0)      { A = A0; W = W0; bias = b0; C = C0; }
    else if (blockIdx.z == 1) { A = A1; W = W1; bias = b1; C = C1; }
    else                      { A = A2; W = W2; bias = b2; C = C2; }

    const int tid  = threadIdx.x;
    const int warp = tid >> 5, lane = tid & 31;
    const int g = lane >> 2, tg = lane & 3;
    const int wm = (warp & 1) * 64, wn = (warp >> 1) * 32;
    const int bm = blockIdx.y * 128, bn = blockIdx.x * 128;

    auto load_stage = [&](int nb, int k0) {
#pragma unroll
        for (int it = 0; it < 4; it++) {
            int idx = it * 256 + tid;
            int ar = idx >> 3, au = idx & 7;
            cp16(&As[nb][ar][au * 4], &A[(size_t)(bm + ar) * 1024 + k0 + au * 4]);
            int br = idx >> 5, bu = idx & 31;
            cp16(&Bs[nb][br][bu * 4], &W[(size_t)(k0 + br) * 1024 + bn + bu * 4]);
        }
        CP_COMMIT;
    };

    load_stage(0, 0);

    float acc[4][4][4] = {};

    for (int k0 = 0; k0 < 1024; k0 += 32) {
        const int buf = (k0 >> 5) & 1;
        CP_WAIT0;
        __syncthreads();
        if (k0 + 32 < 1024) load_stage(buf ^ 1, k0 + 32);
#pragma unroll
        for (int ks = 0; ks < 4; ks++) {
            const int kb = ks * 8;
            unsigned af[4][4], bf[4][2];
#pragma unroll
            for (int mt = 0; mt < 4; mt++) {
                int r = wm + mt * 16;
                af[mt][0] = As[buf][r + g][kb + tg];
                af[mt][1] = As[buf][r + g + 8][kb + tg];
                af[mt][2] = As[buf][r + g][kb + tg + 4];
                af[mt][3] = As[buf][r + g + 8][kb + tg + 4];
            }
#pragma unroll
            for (int nt = 0; nt < 4; nt++) {
                int c = wn + nt * 8 + g;
                bf[nt][0] = Bs[buf][kb + tg][c];
                bf[nt][1] = Bs[buf][kb + tg + 4][c];
            }
#pragma unroll
            for (int mt = 0; mt < 4; mt++)
#pragma unroll
                for (int nt = 0; nt < 4; nt++)
                    mma_tf32(acc[mt][nt], af[mt], bf[nt]);
        }
    }

#pragma unroll
    for (int mt = 0; mt < 4; mt++) {
        int r0 = bm + wm + mt * 16 + g;
#pragma unroll
        for (int nt = 0; nt < 4; nt++) {
            int c0 = bn + wn + nt * 8 + tg * 2;
            float bb0 = bias[c0], bb1 = bias[c0 + 1];
            float v00 = acc[mt][nt][0] + bb0, v01 = acc[mt][nt][1] + bb1;
            float v10 = acc[mt][nt][2] + bb0, v11 = acc[mt][nt][3] + bb1;
            if (rnd) {
                v00 = rndf(v00); v01 = rndf(v01);
                v10 = rndf(v10); v11 = rndf(v11);
            }
            C[(size_t)r0 * 1024 + c0]           = v00;
            C[(size_t)r0 * 1024 + c0 + 1]       = v01;
            C[(size_t)(r0 + 8) * 1024 + c0]     = v10;
            C[(size_t)(r0 + 8) * 1024 + c0 + 1] = v11;
        }
    }
}

// ---------------------------------------------------------------------------
// Scores + exp. 64(q) x 128(k) per CTA, 3/SM. bh0 selects the batch half.
// Dynamic smem: Qs[64][68] + Ks[128][68] = 52224 bytes.
// ---------------------------------------------------------------------------
__global__ __launch_bounds__(256, 3) void scores_exp_tf32_kernel(
    const float* __restrict__ q, const float* __restrict__ k,
    float* __restrict__ attn, int bh0) {
    extern __shared__ unsigned sm[];
    unsigned (*Qs)[68] = (unsigned(*)[68])sm;             // [64][68]
    unsigned (*Ks)[68] = (unsigned(*)[68])(sm + 64 * 68); // [128][68]
    __shared__ float rowred[64];

    const int tid  = threadIdx.x;
    const int warp = tid >> 5, lane = tid & 31;
    const int g = lane >> 2, tg = lane & 3;
    const int wm = (warp & 1) * 32, wn = (warp >> 1) * 32;
    const int bh = blockIdx.z + bh0;
    const int b = bh >> 4, h = bh & 15;
    const int qi0 = blockIdx.y * 64, ki0 = blockIdx.x * 128;
    const float* qb = q + (size_t)b * T1C * DD + h * HDC;
    const float* kb = k + (size_t)b * T2C * DD + h * HDC;

    if (tid < 64) rowred[tid] = 0.0f;

#pragma unroll
    for (int i = 0; i < 4; i++) {
        int idx = tid + i * 256;
        int row = idx >> 4, c4 = (idx & 15) * 4;
        cp16(&Qs[row][c4], &qb[(size_t)(qi0 + row) * DD + c4]);
    }
#pragma unroll
    for (int i = 0; i < 8; i++) {
        int idx = tid + i * 256;
        int row = idx >> 4, c4 = (idx & 15) * 4;
        cp16(&Ks[row][c4], &kb[(size_t)(ki0 + row) * DD + c4]);
    }
    CP_COMMIT;
    CP_WAIT0;
    __syncthreads();

    float acc[2][4][4] = {};
#pragma unroll
    for (int kc = 0; kc < 8; kc++) {
        const int kbk = kc * 8;
        unsigned af[2][4], bf[4][2];
#pragma unroll
        for (int mt = 0; mt < 2; mt++) {
            int r = wm + mt * 16;
            af[mt][0] = Qs[r + g][kbk + tg];
            af[mt][1] = Qs[r + g + 8][kbk + tg];
            af[mt][2] = Qs[r + g][kbk + tg + 4];
            af[mt][3] = Qs[r + g + 8][kbk + tg + 4];
        }
#pragma unroll
        for (int nt = 0; nt < 4; nt++) {
            int c = wn + nt * 8 + g;
            bf[nt][0] = Ks[c][kbk + tg];
            bf[nt][1] = Ks[c][kbk + tg + 4];
        }
#pragma unroll
        for (int mt = 0; mt < 2; mt++)
#pragma unroll
            for (int nt = 0; nt < 4; nt++)
                mma_tf32(acc[mt][nt], af[mt], bf[nt]);
    }

    float* outp = attn + ((size_t)bh * T1C + qi0) * T2C + ki0;
    const float* mb = &g_maskbias[b * T2C + ki0];
#pragma unroll
    for (int mt = 0; mt < 2; mt++) {
        int r0 = wm + mt * 16 + g;
        float rp0 = 0.0f, rp1 = 0.0f;
#pragma unroll
        for (int nt = 0; nt < 4; nt++) {
            int c0 = wn + nt * 8 + tg * 2;
            float m0 = mb[c0], m1 = mb[c0 + 1];
            float2 e0, e1;
            e0.x = rndf(__expf(acc[mt][nt][0] * 0.125f + m0));
            e0.y = rndf(__expf(acc[mt][nt][1] * 0.125f + m1));
            e1.x = rndf(__expf(acc[mt][nt][2] * 0.125f + m0));
            e1.y = rndf(__expf(acc[mt][nt][3] * 0.125f + m1));
            *(float2*)&outp[(size_t)r0 * T2C + c0]       = e0;
            *(float2*)&outp[(size_t)(r0 + 8) * T2C + c0] = e1;
            rp0 += e0.x + e0.y;
            rp1 += e1.x + e1.y;
        }
        rp0 += __shfl_xor_sync(0xffffffffu, rp0, 1);
        rp0 += __shfl_xor_sync(0xffffffffu, rp0, 2);
        rp1 += __shfl_xor_sync(0xffffffffu, rp1, 1);
        rp1 += __shfl_xor_sync(0xffffffffu, rp1, 2);
        if (tg == 0) {
            atomicAdd(&rowred[r0], rp0);
            atomicAdd(&rowred[r0 + 8], rp1);
        }
    }
    __syncthreads();
    if (tid < 64)
        atomicAdd(&g_rowsum[(size_t)bh * T1C + qi0 + tid], rowred[tid]);
}

// ---------------------------------------------------------------------------
// Fused normalize + context. bh0 selects the batch half.
// Dynamic smem: As[2][128][36] + Vs[2][32][72] = 55296 bytes.
// ---------------------------------------------------------------------------
__global__ __launch_bounds__(256, 3) void ctx_tf32_kernel(
    float* __restrict__ attn, const float* __restrict__ v,
    float* __restrict__ ctx, int bh0) {
    extern __shared__ unsigned sm[];
    unsigned (*As)[128][36] = (unsigned(*)[128][36])sm;
    unsigned (*Vs)[32][72]  = (unsigned(*)[32][72])(sm + 2 * 128 * 36);
    __shared__ float invs[128];

    const int tid  = threadIdx.x;
    const int warp = tid >> 5, lane = tid & 31;
    const int g = lane >> 2, tg = lane & 3;
    const int wm = (warp & 3) * 32, wn = (warp >> 2) * 32;
    const int bh = blockIdx.y + bh0;
    const int b = bh >> 4, h = bh & 15;
    const int qi0 = blockIdx.x * 128;
    float* pb = attn + ((size_t)bh * T1C + qi0) * T2C;
    const float* vb = v + (size_t)b * T2C * DD + h * HDC;

    if (tid < 128) invs[tid] = 1.0f / g_rowsum[(size_t)bh * T1C + qi0 + tid];

    const int arow = tid >> 3, ac4 = (tid & 7) * 4;
    const int vrow = tid >> 4, vc4 = (tid & 15) * 4;

    {
        cp16(&As[0][arow][ac4],      &pb[(size_t)arow * T2C + ac4]);
        cp16(&As[0][arow + 32][ac4], &pb[(size_t)(arow + 32) * T2C + ac4]);
        cp16(&As[0][arow + 64][ac4], &pb[(size_t)(arow + 64) * T2C + ac4]);
        cp16(&As[0][arow + 96][ac4], &pb[(size_t)(arow + 96) * T2C + ac4]);
        cp16(&Vs[0][vrow][vc4],      &vb[(size_t)vrow * DD + vc4]);
        cp16(&Vs[0][vrow + 16][vc4], &vb[(size_t)(vrow + 16) * DD + vc4]);
        CP_COMMIT;
    }

    float acc[2][4][4] = {};

    for (int j0 = 0; j0 < T2C; j0 += 32) {
        const int buf = (j0 >> 5) & 1;
        CP_WAIT0;
        __syncthreads();
        if (j0 + 32 < T2C) {
            const int nb = buf ^ 1, jn = j0 + 32;
            cp16(&As[nb][arow][ac4],      &pb[(size_t)arow * T2C + jn + ac4]);
            cp16(&As[nb][arow + 32][ac4], &pb[(size_t)(arow + 32) * T2C + jn + ac4]);
            cp16(&As[nb][arow + 64][ac4], &pb[(size_t)(arow + 64) * T2C + jn + ac4]);
            cp16(&As[nb][arow + 96][ac4], &pb[(size_t)(arow + 96) * T2C + jn + ac4]);
            cp16(&Vs[nb][vrow][vc4],      &vb[(size_t)(jn + vrow) * DD + vc4]);
            cp16(&Vs[nb][vrow + 16][vc4], &vb[(size_t)(jn + vrow + 16) * DD + vc4]);
            CP_COMMIT;
        }

#pragma unroll
        for (int i = 0; i < 4; i++) {
            int row = arow + i * 32;
            float s = invs[row];
            float4 p = *(float4*)&As[buf][row][ac4];
            p.x *= s; p.y *= s; p.z *= s; p.w *= s;
            *(float4*)&pb[(size_t)row * T2C + j0 + ac4] = p;
        }

#pragma unroll
        for (int ks = 0; ks < 4; ks++) {
            const int kb = ks * 8;
            unsigned af[2][4], bf[4][2];
#pragma unroll
            for (int mt = 0; mt < 2; mt++) {
                int r = wm + mt * 16;
                af[mt][0] = As[buf][r + g][kb + tg];
                af[mt][1] = As[buf][r + g + 8][kb + tg];
                af[mt][2] = As[buf][r + g][kb + tg + 4];
                af[mt][3] = As[buf][r + g + 8][kb + tg + 4];
            }
#pragma unroll
            for (int nt = 0; nt < 4; nt++) {
                int c = wn + nt * 8 + g;
                bf[nt][0] = Vs[buf][kb + tg][c];
                bf[nt][1] = Vs[buf][kb + tg + 4][c];
            }
#pragma unroll
            for (int mt = 0; mt < 2; mt++)
#pragma unroll
                for (int nt = 0; nt < 4; nt++)
                    mma_tf32(acc[mt][nt], af[mt], bf[nt]);
        }
    }

#pragma unroll
    for (int mt = 0; mt < 2; mt++) {
        int rloc = wm + mt * 16 + g;
        int r0 = qi0 + rloc;
        float s0 = invs[rloc], s1 = invs[rloc + 8];
#pragma unroll
        for (int nt = 0; nt < 4; nt++) {
            int c0 = wn + nt * 8 + tg * 2;
            size_t base0 = (size_t)b * T1C * DD + (size_t)r0 * DD + h * HDC + c0;
            size_t base1 = base0 + (size_t)8 * DD;
            ctx[base0]     = rndf(acc[mt][nt][0] * s0);
            ctx[base0 + 1] = rndf(acc[mt][nt][1] * s0);
            ctx[base1]     = rndf(acc[mt][nt][2] * s1);
            ctx[base1 + 1] = rndf(acc[mt][nt][3] * s1);
        }
    }
}

// ---------------------------------------------------------------------------
extern "C" void kernel_launch(void* const* d_in, const int* in_sizes, int n_in,
                              void* d_out, int out_size) {
    const float* query = (const float*)d_in[0];
    const float* key   = (const float*)d_in[1];
    const float* value = (const float*)d_in[2];
    const unsigned char* mask = (const unsigned char*)d_in[3];
    const float* Wq_w = (const float*)d_in[4];
    const float* Wq_b = (const float*)d_in[5];
    const float* Wk_w = (const float*)d_in[6];
    const float* Wk_b = (const float*)d_in[7];
    const float* Wv_w = (const float*)d_in[8];
    const float* Wv_b = (const float*)d_in[9];
    const float* Wo_w = (const float*)d_in[10];
    const float* Wo_b = (const float*)d_in[11];

    float* out  = (float*)d_out;                          // [B,T1,D]
    float* attn = out + (size_t)BB * T1C * DD;            // [B,H,T1,T2]

    float *gq, *gk, *gv, *gctx;
    float *grq, *grk, *grv, *grwq, *grwk, *grwv, *grwo;
    cudaGetSymbolAddress((void**)&gq,   g_q);
    cudaGetSymbolAddress((void**)&gk,   g_k);
    cudaGetSymbolAddress((void**)&gv,   g_v);
    cudaGetSymbolAddress((void**)&gctx, g_ctx);
    cudaGetSymbolAddress((void**)&grq,  g_rq);
    cudaGetSymbolAddress((void**)&grk,  g_rk);
    cudaGetSymbolAddress((void**)&grv,  g_rv);
    cudaGetSymbolAddress((void**)&grwq, g_rwq);
    cudaGetSymbolAddress((void**)&grwk, g_rwk);
    cudaGetSymbolAddress((void**)&grwv, g_rwv);
    cudaGetSymbolAddress((void**)&grwo, g_rwo);

    const int scores_smem = ((64 + 128) * 68) * 4;                // 52224
    const int ctx_smem    = (2 * 128 * 36 + 2 * 32 * 72) * 4;     // 55296
    const int gemm_smem   = (2 * 128 * 36 + 2 * 32 * 136) * 4;    // 71680
    cudaFuncSetAttribute(scores_exp_tf32_kernel,
                         cudaFuncAttributeMaxDynamicSharedMemorySize, scores_smem);
    cudaFuncSetAttribute(ctx_tf32_kernel,
                         cudaFuncAttributeMaxDynamicSharedMemorySize, ctx_smem);
    cudaFuncSetAttribute(gemm3_tf32_kernel,
                         cudaFuncAttributeMaxDynamicSharedMemorySize, gemm_smem);

    // Side stream + events (created once; host-side resources only).
    static cudaStream_t s2 = 0;
    static cudaEvent_t evF = 0, evRA = 0, evV = 0, evQK1 = 0, evS0 = 0, evDone = 0;
    if (!s2) {
        cudaStreamCreateWithFlags(&s2, cudaStreamNonBlocking);
        cudaEventCreateWithFlags(&evF,    cudaEventDisableTiming);
        cudaEventCreateWithFlags(&evRA,   cudaEventDisableTiming);
        cudaEventCreateWithFlags(&evV,    cudaEventDisableTiming);
        cudaEventCreateWithFlags(&evQK1,  cudaEventDisableTiming);
        cudaEventCreateWithFlags(&evS0,   cudaEventDisableTiming);
        cudaEventCreateWithFlags(&evDone, cudaEventDisableTiming);
    }

    const size_t halfRows = (size_t)T1C * DD;   // elements per batch half

    // Fork side stream.
    cudaEventRecord(evF, 0);
    cudaStreamWaitEvent(s2, evF, 0);

    // ---- Side stream: V path, then batch-1 QK projection ----
    roundB_kernel<<<dim3(4096, 1, 3), 256, 0, s2>>>(value, Wv_w, Wo_w);
    gemm3_tf32_kernel<<<dim3(8, 32, 1), 256, gemm_smem, s2>>>(
        grv, grwv, Wv_b, gv, grv, grwv, Wv_b, gv, grv, grwv, Wv_b, gv, 1);
    cudaEventRecord(evV, s2);

    // ---- Main stream: prep + roundA + batch-0 QK projection ----
    prep_mask_kernel<<<257, 256>>>(mask);
    roundA_kernel<<<dim3(4096, 1, 4), 256>>>(query, key, Wq_w, Wk_w);
    cudaEventRecord(evRA, 0);
    gemm3_tf32_kernel<<<dim3(8, 16, 2), 256, gemm_smem>>>(
        grq, grwq, Wq_b, gq, grk, grwk, Wk_b, gk, grk, grwk, Wk_b, gk, 1);

    // Side: batch-1 QK projection (needs roundA).
    cudaStreamWaitEvent(s2, evRA, 0);
    gemm3_tf32_kernel<<<dim3(8, 16, 2), 256, gemm_smem, s2>>>(
        grq + halfRows, grwq, Wq_b, gq + halfRows,
        grk + halfRows, grwk, Wk_b, gk + halfRows,
        grk + halfRows, grwk, Wk_b, gk + halfRows, 1);
    cudaEventRecord(evQK1, s2);

    // Main: scores_b0 (only needs batch-0 q,k).
    scores_exp_tf32_kernel<<<dim3(16, 32, 16), 256, scores_smem>>>(gq, gk, attn, 0);
    cudaEventRecord(evS0, 0);

    // Main: scores_b1 (needs batch-1 q,k from side).
    cudaStreamWaitEvent(0, evQK1, 0);
    scores_exp_tf32_kernel<<<dim3(16, 32, 16), 256, scores_smem>>>(gq, gk, attn, 16);

    // Side: ctx_b0 + outproj_b0 (needs scores_b0 + V; evV already in-stream).
    cudaStreamWaitEvent(s2, evS0, 0);
    ctx_tf32_kernel<<<dim3(16, 16), 256, ctx_smem, s2>>>(attn, gv, gctx, 0);
    gemm3_tf32_kernel<<<dim3(8, 16, 1), 256, gemm_smem, s2>>>(
        gctx, grwo, Wo_b, out, gctx, grwo, Wo_b, out, gctx, grwo, Wo_b, out, 0);
    cudaEventRecord(evDone, s2);

    // Main: ctx_b1 (needs V) + outproj_b1, then join.
    cudaStreamWaitEvent(0, evV, 0);
    ctx_tf32_kernel<<<dim3(16, 16), 256, ctx_smem>>>(attn, gv, gctx, 16);
    gemm3_tf32_kernel<<<dim3(8, 16, 1), 256, gemm_smem>>>(
        gctx + halfRows, grwo, Wo_b, out + halfRows,
        gctx + halfRows, grwo, Wo_b, out + halfRows,
        gctx + halfRows, grwo, Wo_b, out + halfRows, 0);
    cudaStreamWaitEvent(0, evDone, 0);
}